// round 1
// baseline (speedup 1.0000x reference)
#include <cuda_runtime.h>

// Problem constants
#define B_   2
#define T_   8
#define BT_  16      // B*T
#define NQ_  128
#define NK_  128
#define DIN_ 64
#define DOUT_ 256
#define DCH_ 64      // d-chunk staged in shared per iteration

// Scratch for projected Q and K (device globals: allocation-free per harness rules)
__device__ float g_Q[B_ * NQ_ * DOUT_];            // 256 rows x 256
__device__ float g_K[BT_ * NK_ * DOUT_];           // 2048 rows x 256

// ---------------------------------------------------------------------------
// Kernel 1: projections.
//   g_Q[r, c] = sum_i query[r, i] * Wq[i, c]                (r in [0,256))
//   g_K[r, c] = sum_i keys [r, i] * Wk[i, c] + bk[c]        (r in [0,2048))
// Block = 16 rows x 256 cols. Thread tile = 4 rows x 4 cols (float4 accs),
// W loaded as float4 column-groups into registers (coalesced LDG.128),
// input rows staged in shared (broadcast float4 LDS). FMA-bound.
// ---------------------------------------------------------------------------
__global__ void __launch_bounds__(256) proj_kernel(
    const float* __restrict__ query, const float* __restrict__ keys,
    const float* __restrict__ Wq,    const float* __restrict__ Wk,
    const float* __restrict__ bk)
{
    __shared__ float in_sh[16][DIN_];

    const int blk = blockIdx.x;            // 0..143 (16 Q blocks, 128 K blocks)
    const bool isQ = (blk < 16);
    const int r0 = (isQ ? blk : (blk - 16)) * 16;
    const float* __restrict__ in = isQ ? query : keys;
    const float* __restrict__ W  = isQ ? Wq    : Wk;
    float* __restrict__ outb     = isQ ? g_Q   : g_K;

    const int tid = threadIdx.x;
    const int cg = tid & 63;                // column group: cols 4*cg..4*cg+3
    const int rg = tid >> 6;                // row group: rows rg*4..rg*4+3

    // Stage the 16 input rows (16 rows x 16 float4 = 256 float4, 1/thread)
    {
        const int r = tid >> 4, s = tid & 15;
        *(float4*)&in_sh[r][s * 4] =
            *(const float4*)(in + (size_t)(r0 + r) * DIN_ + s * 4);
    }
    __syncthreads();

    float4 bias = make_float4(0.f, 0.f, 0.f, 0.f);
    if (!isQ) bias = *(const float4*)(bk + cg * 4);

    float4 acc[4];
#pragma unroll
    for (int rr = 0; rr < 4; rr++) acc[rr] = bias;

#pragma unroll
    for (int ic = 0; ic < 8; ic++) {        // i-chunks of 8 over DIN_=64
        float4 wv[8];
#pragma unroll
        for (int i = 0; i < 8; i++)
            wv[i] = *(const float4*)(W + (size_t)(ic * 8 + i) * DOUT_ + cg * 4);
#pragma unroll
        for (int rr = 0; rr < 4; rr++) {
            const int row = rg * 4 + rr;
#pragma unroll
            for (int i4 = 0; i4 < 2; i4++) {
                float4 xv = *(const float4*)&in_sh[row][ic * 8 + i4 * 4];
#pragma unroll
                for (int q = 0; q < 4; q++) {
                    const float x = (q == 0) ? xv.x : (q == 1) ? xv.y
                                  : (q == 2) ? xv.z : xv.w;
                    const float4 w4 = wv[i4 * 4 + q];
                    acc[rr].x = fmaf(x, w4.x, acc[rr].x);
                    acc[rr].y = fmaf(x, w4.y, acc[rr].y);
                    acc[rr].z = fmaf(x, w4.z, acc[rr].z);
                    acc[rr].w = fmaf(x, w4.w, acc[rr].w);
                }
            }
        }
    }

#pragma unroll
    for (int rr = 0; rr < 4; rr++)
        *(float4*)&outb[(size_t)(r0 + rg * 4 + rr) * DOUT_ + cg * 4] = acc[rr];
}

// ---------------------------------------------------------------------------
// Kernel 2: scores + fused softmax.
// Grid: B*T*(NQ/8) = 256 blocks, 256 threads (8 warps).
// Warp w -> query row q0+w. Lane l -> nk in {l, l+32, l+64, l+96}
// (lane-strided nk: pitch-65 shared rows give conflict-free scalar LDS,
//  and output stores stay coalesced per 32-lane group).
// K staged in 4 chunks of 64 d-values (33KB smem -> whole grid resident).
// tanh via MUFU.TANH (1 MUFU/element -> binding pipe).
// ---------------------------------------------------------------------------
__global__ void __launch_bounds__(256) attn_kernel(
    const float* __restrict__ v, float* __restrict__ out)
{
    __shared__ float k_sh[NK_][DCH_ + 1];   // pitch 65 floats
    __shared__ float q_sh[8][DCH_];
    __shared__ float v_sh[DCH_];

    const int bt = blockIdx.x >> 4;         // 0..15 = b*T + t
    const int q0 = (blockIdx.x & 15) << 3;  // query-row chunk of 8
    const int b  = bt >> 3;

    const int tid  = threadIdx.x;
    const int w    = tid >> 5;
    const int lane = tid & 31;

    const float* __restrict__ kbase = g_K + (size_t)(bt * NK_) * DOUT_;
    const float* __restrict__ qbase = g_Q + (size_t)(b * NQ_ + q0) * DOUT_;

    float acc0 = 0.f, acc1 = 0.f, acc2 = 0.f, acc3 = 0.f;

#pragma unroll 1
    for (int c = 0; c < DOUT_ / DCH_; c++) {
        const int d0 = c * DCH_;

        // Stage K chunk: 128 rows x 16 float4 = 2048 float4 (8/thread)
#pragma unroll
        for (int e = tid; e < NK_ * 16; e += 256) {
            const int nk = e >> 4, s = e & 15;
            float4 t = *(const float4*)(kbase + (size_t)nk * DOUT_ + d0 + s * 4);
            k_sh[nk][s * 4 + 0] = t.x;
            k_sh[nk][s * 4 + 1] = t.y;
            k_sh[nk][s * 4 + 2] = t.z;
            k_sh[nk][s * 4 + 3] = t.w;
        }
        // Stage Q chunk: 8 rows x 16 float4
        if (tid < 128) {
            const int r = tid >> 4, s = tid & 15;
            *(float4*)&q_sh[r][s * 4] =
                *(const float4*)(qbase + (size_t)r * DOUT_ + d0 + s * 4);
        }
        // Stage v chunk
        if (tid < 16)
            *(float4*)&v_sh[tid * 4] = *(const float4*)(v + d0 + tid * 4);

        __syncthreads();

#pragma unroll 4
        for (int d4 = 0; d4 < DCH_; d4 += 4) {
            const float4 qv = *(const float4*)&q_sh[w][d4];
            const float4 vv = *(const float4*)&v_sh[d4];
#pragma unroll
            for (int dd = 0; dd < 4; dd++) {
                const float qd = (dd == 0) ? qv.x : (dd == 1) ? qv.y
                               : (dd == 2) ? qv.z : qv.w;
                const float vd = (dd == 0) ? vv.x : (dd == 1) ? vv.y
                               : (dd == 2) ? vv.z : vv.w;
                const int d = d4 + dd;
                const float s0 = qd + k_sh[lane      ][d];
                const float s1 = qd + k_sh[lane + 32 ][d];
                const float s2 = qd + k_sh[lane + 64 ][d];
                const float s3 = qd + k_sh[lane + 96 ][d];
                float t0, t1, t2, t3;
                asm("tanh.approx.f32 %0, %1;" : "=f"(t0) : "f"(s0));
                asm("tanh.approx.f32 %0, %1;" : "=f"(t1) : "f"(s1));
                asm("tanh.approx.f32 %0, %1;" : "=f"(t2) : "f"(s2));
                asm("tanh.approx.f32 %0, %1;" : "=f"(t3) : "f"(s3));
                acc0 = fmaf(vd, t0, acc0);
                acc1 = fmaf(vd, t1, acc1);
                acc2 = fmaf(vd, t2, acc2);
                acc3 = fmaf(vd, t3, acc3);
            }
        }
        __syncthreads();
    }

    // Fused softmax over nk (warp owns the full 128-wide row)
    float m = fmaxf(fmaxf(acc0, acc1), fmaxf(acc2, acc3));
#pragma unroll
    for (int o = 16; o > 0; o >>= 1)
        m = fmaxf(m, __shfl_xor_sync(0xffffffffu, m, o));

    const float e0 = __expf(acc0 - m);
    const float e1 = __expf(acc1 - m);
    const float e2 = __expf(acc2 - m);
    const float e3 = __expf(acc3 - m);
    float ssum = e0 + e1 + e2 + e3;
#pragma unroll
    for (int o = 16; o > 0; o >>= 1)
        ssum += __shfl_xor_sync(0xffffffffu, ssum, o);

    const float rinv = 1.0f / ssum;

    float* __restrict__ orow = out + (size_t)(bt * NQ_ + q0 + w) * NK_;
    orow[lane      ] = e0 * rinv;
    orow[lane + 32 ] = e1 * rinv;
    orow[lane + 64 ] = e2 * rinv;
    orow[lane + 96 ] = e3 * rinv;
}

// ---------------------------------------------------------------------------
extern "C" void kernel_launch(void* const* d_in, const int* in_sizes, int n_in,
                              void* d_out, int out_size)
{
    const float* query = (const float*)d_in[0];
    const float* keys  = (const float*)d_in[1];
    const float* Wq    = (const float*)d_in[2];
    const float* Wk    = (const float*)d_in[3];
    const float* bk    = (const float*)d_in[4];
    const float* v     = (const float*)d_in[5];
    float* out = (float*)d_out;

    proj_kernel<<<144, 256>>>(query, keys, Wq, Wk, bk);
    attn_kernel<<<256, 256>>>(v, out);
}

// round 3
// speedup vs baseline: 1.0955x; 1.0955x over previous
#include <cuda_runtime.h>
#include <cuda_fp16.h>

// Problem constants
#define B_   2
#define T_   8
#define BT_  16
#define NQ_  128
#define NK_  128
#define DIN_ 64
#define DOUT_ 256
#define DP_  128     // d-pairs (DOUT_/2), half2-packed along d
#define DPC_ 64      // d-pairs per staged chunk

// Projected Q/K in half2 (packed d-pairs). Device globals = legal scratch.
__device__ __half2 g_Qh[B_ * NQ_ * DP_];     // 256 rows x 128 half2
__device__ __half2 g_Kh[BT_ * NK_ * DP_];    // 2048 rows x 128 half2

__device__ __forceinline__ __half2 h2tanh_mufu(__half2 x) {
    __half2 r;
    asm("tanh.approx.f16x2 %0, %1;"
        : "=r"(*reinterpret_cast<unsigned*>(&r))
        : "r"(*reinterpret_cast<unsigned*>(&x)));
    return r;
}

// ---------------------------------------------------------------------------
// Kernel 1: projections (fp32 math, half2 output).
//   g_Qh[r, :] = half2(query[r,:] @ Wq)
//   g_Kh[r, :] = half2(keys [r,:] @ Wk + bk)
// ---------------------------------------------------------------------------
__global__ void __launch_bounds__(256) proj_kernel(
    const float* __restrict__ query, const float* __restrict__ keys,
    const float* __restrict__ Wq,    const float* __restrict__ Wk,
    const float* __restrict__ bk)
{
    __shared__ float in_sh[16][DIN_];

    const int blk = blockIdx.x;            // 0..143 (16 Q blocks, 128 K blocks)
    const bool isQ = (blk < 16);
    const int r0 = (isQ ? blk : (blk - 16)) * 16;
    const float* __restrict__ in = isQ ? query : keys;
    const float* __restrict__ W  = isQ ? Wq    : Wk;
    __half2* __restrict__ outb   = isQ ? g_Qh  : g_Kh;

    const int tid = threadIdx.x;
    const int cg = tid & 63;                // cols 4*cg..4*cg+3 -> dpairs 2cg,2cg+1
    const int rg = tid >> 6;                // rows rg*4..rg*4+3

    {
        const int r = tid >> 4, s = tid & 15;
        *(float4*)&in_sh[r][s * 4] =
            *(const float4*)(in + (size_t)(r0 + r) * DIN_ + s * 4);
    }
    __syncthreads();

    float4 bias = make_float4(0.f, 0.f, 0.f, 0.f);
    if (!isQ) bias = *(const float4*)(bk + cg * 4);

    float4 acc[4];
#pragma unroll
    for (int rr = 0; rr < 4; rr++) acc[rr] = bias;

#pragma unroll
    for (int ic = 0; ic < 8; ic++) {
        float4 wv[8];
#pragma unroll
        for (int i = 0; i < 8; i++)
            wv[i] = *(const float4*)(W + (size_t)(ic * 8 + i) * DOUT_ + cg * 4);
#pragma unroll
        for (int rr = 0; rr < 4; rr++) {
            const int row = rg * 4 + rr;
#pragma unroll
            for (int i4 = 0; i4 < 2; i4++) {
                float4 xv = *(const float4*)&in_sh[row][ic * 8 + i4 * 4];
#pragma unroll
                for (int q = 0; q < 4; q++) {
                    const float x = (q == 0) ? xv.x : (q == 1) ? xv.y
                                  : (q == 2) ? xv.z : xv.w;
                    const float4 w4 = wv[i4 * 4 + q];
                    acc[rr].x = fmaf(x, w4.x, acc[rr].x);
                    acc[rr].y = fmaf(x, w4.y, acc[rr].y);
                    acc[rr].z = fmaf(x, w4.z, acc[rr].z);
                    acc[rr].w = fmaf(x, w4.w, acc[rr].w);
                }
            }
        }
    }

#pragma unroll
    for (int rr = 0; rr < 4; rr++) {
        __half2 p0 = __floats2half2_rn(acc[rr].x, acc[rr].y);
        __half2 p1 = __floats2half2_rn(acc[rr].z, acc[rr].w);
        __half2* dst = outb + (size_t)(r0 + rg * 4 + rr) * DP_ + cg * 2;
        dst[0] = p0;
        dst[1] = p1;
    }
}

// ---------------------------------------------------------------------------
// Kernel 2: scores + fused softmax, half2 datapath.
// Grid 256 x 256 thr. Warp w -> query row q0+w; lane l -> nk {l,l+32,l+64,l+96}.
// K chunk (128 nk x 64 dpairs, pitch 65 half2 -> conflict-free LDS.32).
// tanh.approx.f16x2: 1 MUFU per 2 elements. HFMA2 accumulate, fp32 flush
// every 8 d-pairs to bound fp16 rounding.
// ---------------------------------------------------------------------------
__global__ void __launch_bounds__(256) attn_kernel(
    const float* __restrict__ v, float* __restrict__ out)
{
    __shared__ __half2 k_sh[NK_ * (DPC_ + 1)];   // [nk][dp], pitch 65
    __shared__ __half2 q_sh[8][DPC_];
    __shared__ __half2 v_sh[DPC_];

    const int bt = blockIdx.x >> 4;
    const int q0 = (blockIdx.x & 15) << 3;
    const int b  = bt >> 3;

    const int tid  = threadIdx.x;
    const int w    = tid >> 5;
    const int lane = tid & 31;

    const __half2* __restrict__ kbase = g_Kh + (size_t)(bt * NK_) * DP_;
    const __half2* __restrict__ qbase = g_Qh + (size_t)(b * NQ_ + q0) * DP_;

    float acc0 = 0.f, acc1 = 0.f, acc2 = 0.f, acc3 = 0.f;

#pragma unroll 1
    for (int c = 0; c < DP_ / DPC_; c++) {
        const int d0 = c * DPC_;

        // Stage K chunk: 128 rows x 16 uint4 (8 per thread)
#pragma unroll
        for (int e = tid; e < NK_ * 16; e += 256) {
            const int nk = e >> 4, s = e & 15;
            uint4 t = *(const uint4*)(kbase + (size_t)nk * DP_ + d0 + s * 4);
            __half2* dst = &k_sh[nk * (DPC_ + 1) + s * 4];
            *(unsigned*)&dst[0] = t.x;
            *(unsigned*)&dst[1] = t.y;
            *(unsigned*)&dst[2] = t.z;
            *(unsigned*)&dst[3] = t.w;
        }
        // Stage Q chunk: 8 rows x 16 uint4
        if (tid < 128) {
            const int r = tid >> 4, s = tid & 15;
            *(uint4*)&q_sh[r][s * 4] =
                *(const uint4*)(qbase + (size_t)r * DP_ + d0 + s * 4);
        }
        // Stage v chunk (convert fp32 -> half2 on the fly)
        if (tid < DPC_) {
            float2 vv = *(const float2*)(v + 2 * (d0 + tid));
            v_sh[tid] = __floats2half2_rn(vv.x, vv.y);
        }
        __syncthreads();

        const __half2* __restrict__ k0p = &k_sh[(lane      ) * (DPC_ + 1)];
        const __half2* __restrict__ k1p = &k_sh[(lane + 32 ) * (DPC_ + 1)];
        const __half2* __restrict__ k2p = &k_sh[(lane + 64 ) * (DPC_ + 1)];
        const __half2* __restrict__ k3p = &k_sh[(lane + 96 ) * (DPC_ + 1)];

#pragma unroll 2
        for (int dp8 = 0; dp8 < DPC_; dp8 += 8) {
            // Vectorized q/v loads for this 8-dpair block
            uint4 qa = *(const uint4*)&q_sh[w][dp8];
            uint4 qb4 = *(const uint4*)&q_sh[w][dp8 + 4];
            uint4 va = *(const uint4*)&v_sh[dp8];
            uint4 vb4 = *(const uint4*)&v_sh[dp8 + 4];
            unsigned qr[8] = {qa.x, qa.y, qa.z, qa.w, qb4.x, qb4.y, qb4.z, qb4.w};
            unsigned vr[8] = {va.x, va.y, va.z, va.w, vb4.x, vb4.y, vb4.z, vb4.w};

            __half2 h0 = __float2half2_rn(0.f);
            __half2 h1 = h0, h2 = h0, h3 = h0;
#pragma unroll
            for (int j = 0; j < 8; j++) {
                const int dp = dp8 + j;
                const __half2 qp = *reinterpret_cast<const __half2*>(&qr[j]);
                const __half2 vp = *reinterpret_cast<const __half2*>(&vr[j]);
                __half2 t0 = h2tanh_mufu(__hadd2(qp, k0p[dp]));
                __half2 t1 = h2tanh_mufu(__hadd2(qp, k1p[dp]));
                __half2 t2 = h2tanh_mufu(__hadd2(qp, k2p[dp]));
                __half2 t3 = h2tanh_mufu(__hadd2(qp, k3p[dp]));
                h0 = __hfma2(vp, t0, h0);
                h1 = __hfma2(vp, t1, h1);
                h2 = __hfma2(vp, t2, h2);
                h3 = __hfma2(vp, t3, h3);
            }
            // Flush fp16 sub-accumulators to fp32 (8-term chains)
            float2 f0 = __half22float2(h0);
            float2 f1 = __half22float2(h1);
            float2 f2 = __half22float2(h2);
            float2 f3 = __half22float2(h3);
            acc0 += f0.x + f0.y;
            acc1 += f1.x + f1.y;
            acc2 += f2.x + f2.y;
            acc3 += f3.x + f3.y;
        }
        __syncthreads();
    }

    // Fused softmax over nk (warp owns the full 128-wide row)
    float m = fmaxf(fmaxf(acc0, acc1), fmaxf(acc2, acc3));
#pragma unroll
    for (int o = 16; o > 0; o >>= 1)
        m = fmaxf(m, __shfl_xor_sync(0xffffffffu, m, o));

    const float e0 = __expf(acc0 - m);
    const float e1 = __expf(acc1 - m);
    const float e2 = __expf(acc2 - m);
    const float e3 = __expf(acc3 - m);
    float ssum = e0 + e1 + e2 + e3;
#pragma unroll
    for (int o = 16; o > 0; o >>= 1)
        ssum += __shfl_xor_sync(0xffffffffu, ssum, o);

    const float rinv = 1.0f / ssum;

    float* __restrict__ orow = out + (size_t)(bt * NQ_ + q0 + w) * NK_;
    orow[lane      ] = e0 * rinv;
    orow[lane + 32 ] = e1 * rinv;
    orow[lane + 64 ] = e2 * rinv;
    orow[lane + 96 ] = e3 * rinv;
}

// ---------------------------------------------------------------------------
extern "C" void kernel_launch(void* const* d_in, const int* in_sizes, int n_in,
                              void* d_out, int out_size)
{
    const float* query = (const float*)d_in[0];
    const float* keys  = (const float*)d_in[1];
    const float* Wq    = (const float*)d_in[2];
    const float* Wk    = (const float*)d_in[3];
    const float* bk    = (const float*)d_in[4];
    const float* v     = (const float*)d_in[5];
    float* out = (float*)d_out;

    proj_kernel<<<144, 256>>>(query, keys, Wq, Wk, bk);
    attn_kernel<<<256, 256>>>(v, out);
}